// round 8
// baseline (speedup 1.0000x reference)
#include <cuda_runtime.h>

// LinearChainCRF: mean(logZ - gold) over B=16384 sequences of T=512, N_TAGS=4.
//
// Algebra: the reference's logsumexp is over the LAST axis (j); alpha[i] is
// constant in j, so the "scan" is purely additive:
//   alpha_T[i] = em[0,i] + sum_{t>=1} mask_t * log(s_i(t)),
//   s_i(t)     = sum_j exp(trans[i,j]) * exp(em[t,j])   (|e| <~ 6 -> no norm)
//   logZ       = logsumexp_i(alpha_T[i]);  result = mean(logZ - gold).
//
// R8: block = 128 threads = 4 warps = ONE sequence (4 t/thread, stride-32 ->
// emission LDG.128 wavefronts stay 4 lines). 16384 short blocks kill the
// coarse-wave tail that R7's profile exposed (2.31 waves of 24us at 6 blk/SM).
// Products replace per-t logs (4-product range [4e-26, 2.2e13], fp32-safe).
// Mean: per-block Q32.32 integer atomicAdd into 64 buckets (associative ->
// deterministic); ticketed last block folds buckets, writes out, re-zeros.

#define T_LEN 512
#define NTHREADS 128
#define NBUCKETS 64
#define FIXED_SCALE 4294967296.0   // 2^32

__device__ unsigned long long g_buckets[NBUCKETS];  // zero at load; self-reset
__device__ unsigned int g_ticket;                   // used modulo grid size

__global__ __launch_bounds__(NTHREADS)
void crf_kernel(const float* __restrict__ emissions,
                const void* __restrict__ tags_raw,
                const void* __restrict__ mask_raw,
                const float* __restrict__ transitions,
                float* __restrict__ out, int B)
{
    __shared__ float trans_s[16];
    __shared__ float expT_s[16];
    __shared__ float wsum[4][5];
    __shared__ float alpha0_s[4];
    __shared__ int s_last;

    const int lane = threadIdx.x & 31;
    const int warp = threadIdx.x >> 5;
    const int b = blockIdx.x;
    const unsigned full = 0xffffffffu;

    if (threadIdx.x < 16) {
        float tv = transitions[threadIdx.x];
        trans_s[threadIdx.x] = tv;
        expT_s[threadIdx.x] = __expf(tv);
    }
    __syncthreads();

    // ---- dtype probes on first words (L1/L2-resident after first blocks) ----
    const int* tags32p = (const int*)tags_raw;
    const unsigned int* mask32p = (const unsigned int*)mask_raw;
    // tags int64 <=> odd int32 words all zero (tags in [0,4))
    const int tag_is64 = (__ballot_sync(full, tags32p[2 * lane + 1] != 0) == 0u);
    // mask: u8 -> hi bytes set in words; i32 -> odd words nonzero; i64 -> neither
    const unsigned int hi = __ballot_sync(full, (mask32p[lane] & 0xFFFFFF00u) != 0u);
    const unsigned int od = __ballot_sync(full, mask32p[2 * lane + 1] != 0u);
    const int mask_w = hi ? 1 : (od ? 4 : 8);

    float eT[16];
    #pragma unroll
    for (int i = 0; i < 16; ++i) eT[i] = expT_s[i];

    const long long base = (long long)b * T_LEN;
    const float4* em4 = (const float4*)emissions;
    const long long* tg64 = (const long long*)tags_raw;
    const int* tg32 = (const int*)tags_raw;

    float c0, c1, c2, c3, gold = 0.f;
    float pr0 = 1.f, pr1 = 1.f, pr2 = 1.f, pr3 = 1.f;
    float a0 = 0.f, a1 = 0.f, a2 = 0.f, a3 = 0.f;   // alpha0 (thread 0 only)

    #pragma unroll
    for (int i = 0; i < 4; ++i) {
        const int t = warp * 128 + i * 32 + lane;
        const long long idx = base + t;

        const float4 e = em4[idx];

        int tag, ptag = 0;
        if (tag_is64) {
            tag = (int)tg64[idx];
            if (t > 0) ptag = (int)tg64[idx - 1];
        } else {
            tag = tg32[idx];
            if (t > 0) ptag = tg32[idx - 1];
        }
        float m;
        if (mask_w == 1)      m = ((const unsigned char*)mask_raw)[idx] ? 1.0f : 0.0f;
        else if (mask_w == 4) m = ((const int*)mask_raw)[idx] ? 1.0f : 0.0f;
        else                  m = ((const long long*)mask_raw)[idx] ? 1.0f : 0.0f;

        const float etag = (tag == 0) ? e.x : (tag == 1) ? e.y : (tag == 2) ? e.z : e.w;

        if (t == 0) {
            gold += m * etag;
            a0 = e.x; a1 = e.y; a2 = e.z; a3 = e.w;
        } else {
            gold += m * (etag + trans_s[ptag * 4 + tag]);
            const float q0 = __expf(e.x);
            const float q1 = __expf(e.y);
            const float q2 = __expf(e.z);
            const float q3 = __expf(e.w);
            float s0 = eT[0]  * q0 + eT[1]  * q1 + eT[2]  * q2 + eT[3]  * q3;
            float s1 = eT[4]  * q0 + eT[5]  * q1 + eT[6]  * q2 + eT[7]  * q3;
            float s2 = eT[8]  * q0 + eT[9]  * q1 + eT[10] * q2 + eT[11] * q3;
            float s3 = eT[12] * q0 + eT[13] * q1 + eT[14] * q2 + eT[15] * q3;
            pr0 *= (m != 0.f) ? s0 : 1.0f;
            pr1 *= (m != 0.f) ? s1 : 1.0f;
            pr2 *= (m != 0.f) ? s2 : 1.0f;
            pr3 *= (m != 0.f) ? s3 : 1.0f;
        }
    }
    c0 = __logf(pr0);
    c1 = __logf(pr1);
    c2 = __logf(pr2);
    c3 = __logf(pr3);

    // warp-wide sums of {c0,c1,c2,c3,gold}
    float v[5] = {c0, c1, c2, c3, gold};
    #pragma unroll
    for (int k = 0; k < 5; ++k) {
        float x = v[k];
        x += __shfl_xor_sync(full, x, 16);
        x += __shfl_xor_sync(full, x, 8);
        x += __shfl_xor_sync(full, x, 4);
        x += __shfl_xor_sync(full, x, 2);
        x += __shfl_xor_sync(full, x, 1);
        v[k] = x;
    }
    if (lane == 0) {
        #pragma unroll
        for (int k = 0; k < 5; ++k) wsum[warp][k] = v[k];
    }
    if (threadIdx.x == 0) {
        alpha0_s[0] = a0; alpha0_s[1] = a1; alpha0_s[2] = a2; alpha0_s[3] = a3;
    }
    __syncthreads();

    if (threadIdx.x == 0) {
        float S[5];
        #pragma unroll
        for (int k = 0; k < 5; ++k)
            S[k] = wsum[0][k] + wsum[1][k] + wsum[2][k] + wsum[3][k];
        const float f0 = alpha0_s[0] + S[0];
        const float f1 = alpha0_s[1] + S[1];
        const float f2 = alpha0_s[2] + S[2];
        const float f3 = alpha0_s[3] + S[3];
        const float mx = fmaxf(fmaxf(f0, f1), fmaxf(f2, f3));
        const float logZ = mx + __logf(__expf(f0 - mx) + __expf(f1 - mx) +
                                       __expf(f2 - mx) + __expf(f3 - mx));
        const float r = logZ - S[4];

        // Deterministic fixed-point accumulation (integer adds are associative).
        long long q = llrint((double)r * FIXED_SCALE);
        atomicAdd(&g_buckets[b & (NBUCKETS - 1)], (unsigned long long)q);
        __threadfence();
        unsigned int old = atomicAdd(&g_ticket, 1u);
        // 2^32 % gridDim.x == 0 (grid = 16384 = 2^14): replay-safe without reset.
        s_last = ((old % gridDim.x) == gridDim.x - 1u);
    }
    __syncthreads();

    if (s_last && threadIdx.x == 0) {
        long long total = 0;
        #pragma unroll
        for (int i = 0; i < NBUCKETS; ++i)
            total += (long long)g_buckets[i];
        out[0] = (float)(((double)total / FIXED_SCALE) / (double)B);
        // Re-zero for the next graph replay (only this block runs here).
        #pragma unroll
        for (int i = 0; i < NBUCKETS; ++i)
            g_buckets[i] = 0ULL;
    }
}

extern "C" void kernel_launch(void* const* d_in, const int* in_sizes, int n_in,
                              void* d_out, int out_size)
{
    const float* emissions   = (const float*)d_in[0];
    const void*  tags        = (const void*)d_in[1];
    const void*  mask        = (const void*)d_in[2];
    const float* transitions = (const float*)d_in[3];

    const int B = in_sizes[0] / (T_LEN * 4);   // emissions: B*T*4 floats

    crf_kernel<<<B, NTHREADS>>>(emissions, tags, mask, transitions,
                                (float*)d_out, B);
}

// round 9
// speedup vs baseline: 1.3219x; 1.3219x over previous
#include <cuda_runtime.h>

// LinearChainCRF: mean(logZ - gold) over B=16384 sequences of T=512, N_TAGS=4.
//
// Algebra: the reference's logsumexp is over the LAST axis (j); alpha[i] is
// constant in j, so the "scan" is purely additive:
//   alpha_T[i] = em[0,i] + sum_{t>=1} mask_t * log(s_i(t)),
//   s_i(t)     = sum_j exp(trans[i,j]) * exp(em[t,j])   (|e| <~ 6 -> no norm)
//   logZ       = logsumexp_i(alpha_T[i]);  result = mean(logZ - gold).
//
// R9 = R4's best-measured hot loop (warp-per-sequence, 16 t/thread stride-32,
// all loads independent, eT in registers, 256-thread blocks, grid 2048)
// + fused deterministic reduction (Q32.32 integer bucket atomics + ticket,
// proven in R8) + 32-bit indexing. No smem pad, no launch-bounds cap.

#define T_LEN 512
#define WARPS_PER_BLOCK 8
#define NTHREADS (32 * WARPS_PER_BLOCK)
#define NBUCKETS 64
#define FIXED_SCALE 4294967296.0   // 2^32

__device__ unsigned long long g_buckets[NBUCKETS];  // zero at load; self-reset
__device__ unsigned int g_ticket;                   // used modulo grid size

__global__ __launch_bounds__(NTHREADS)
void crf_warp_kernel(const float* __restrict__ emissions,
                     const void* __restrict__ tags_raw,
                     const void* __restrict__ mask_raw,
                     const float* __restrict__ transitions,
                     float* __restrict__ out, int B)
{
    __shared__ float trans_s[16];
    __shared__ float expT_s[16];
    __shared__ int s_last;

    const int lane = threadIdx.x & 31;
    const int warp = threadIdx.x >> 5;
    const int b = blockIdx.x * WARPS_PER_BLOCK + warp;
    const unsigned full = 0xffffffffu;

    if (threadIdx.x < 16) {
        float tv = transitions[threadIdx.x];
        trans_s[threadIdx.x] = tv;
        expT_s[threadIdx.x] = __expf(tv);
    }
    __syncthreads();

    // ---- warp-parallel dtype probes (first words; L2-resident after block 0) --
    const int* tags32p = (const int*)tags_raw;
    const unsigned int* mask32p = (const unsigned int*)mask_raw;
    // tags int64 <=> odd int32 words all zero (tags in [0,4); P(miss)~(1/4)^32)
    const int tag_is64 = (__ballot_sync(full, tags32p[2 * lane + 1] != 0) == 0u);
    // mask: u8 -> hi bytes of words set; i32 -> odd words nonzero; i64 -> neither
    const unsigned int hi = __ballot_sync(full, (mask32p[lane] & 0xFFFFFF00u) != 0u);
    const unsigned int od = __ballot_sync(full, mask32p[2 * lane + 1] != 0u);
    const int mask_w = hi ? 1 : (od ? 4 : 8);

    float eT[16];
    #pragma unroll
    for (int i = 0; i < 16; ++i) eT[i] = expT_s[i];

    const int base = b * T_LEN;                      // <= 8.4M: 32-bit safe
    const float4* em4 = (const float4*)emissions;
    const long long* tg64 = (const long long*)tags_raw;
    const int* tg32 = (const int*)tags_raw;

    float c0 = 0.f, c1 = 0.f, c2 = 0.f, c3 = 0.f, gold = 0.f;
    float a0 = 0.f, a1 = 0.f, a2 = 0.f, a3 = 0.f;   // alpha0 (lane 0 only)

    #pragma unroll
    for (int chunk = 0; chunk < 4; ++chunk) {
        float pr0 = 1.f, pr1 = 1.f, pr2 = 1.f, pr3 = 1.f;
        #pragma unroll
        for (int u = 0; u < 4; ++u) {
            const int t = (chunk * 4 + u) * 32 + lane;
            const int idx = base + t;

            const float4 e = em4[idx];

            int tag, ptag = 0;
            if (tag_is64) {
                tag = (int)tg64[idx];
                if (t > 0) ptag = (int)tg64[idx - 1];
            } else {
                tag = tg32[idx];
                if (t > 0) ptag = tg32[idx - 1];
            }
            float m;
            if (mask_w == 1)      m = ((const unsigned char*)mask_raw)[idx] ? 1.0f : 0.0f;
            else if (mask_w == 4) m = ((const int*)mask_raw)[idx] ? 1.0f : 0.0f;
            else                  m = ((const long long*)mask_raw)[idx] ? 1.0f : 0.0f;

            const float etag = (tag == 0) ? e.x : (tag == 1) ? e.y : (tag == 2) ? e.z : e.w;

            if (t == 0) {
                gold += m * etag;
                a0 = e.x; a1 = e.y; a2 = e.z; a3 = e.w;
            } else {
                gold += m * (etag + trans_s[ptag * 4 + tag]);
                const float q0 = __expf(e.x);
                const float q1 = __expf(e.y);
                const float q2 = __expf(e.z);
                const float q3 = __expf(e.w);
                float s0 = eT[0]  * q0 + eT[1]  * q1 + eT[2]  * q2 + eT[3]  * q3;
                float s1 = eT[4]  * q0 + eT[5]  * q1 + eT[6]  * q2 + eT[7]  * q3;
                float s2 = eT[8]  * q0 + eT[9]  * q1 + eT[10] * q2 + eT[11] * q3;
                float s3 = eT[12] * q0 + eT[13] * q1 + eT[14] * q2 + eT[15] * q3;
                pr0 *= (m != 0.f) ? s0 : 1.0f;
                pr1 *= (m != 0.f) ? s1 : 1.0f;
                pr2 *= (m != 0.f) ? s2 : 1.0f;
                pr3 *= (m != 0.f) ? s3 : 1.0f;
            }
        }
        c0 += __logf(pr0);
        c1 += __logf(pr1);
        c2 += __logf(pr2);
        c3 += __logf(pr3);
    }

    // warp-wide sums of {c0,c1,c2,c3,gold}
    float v[5] = {c0, c1, c2, c3, gold};
    #pragma unroll
    for (int k = 0; k < 5; ++k) {
        float x = v[k];
        x += __shfl_xor_sync(full, x, 16);
        x += __shfl_xor_sync(full, x, 8);
        x += __shfl_xor_sync(full, x, 4);
        x += __shfl_xor_sync(full, x, 2);
        x += __shfl_xor_sync(full, x, 1);
        v[k] = x;
    }

    if (lane == 0) {
        const float f0 = a0 + v[0];
        const float f1 = a1 + v[1];
        const float f2 = a2 + v[2];
        const float f3 = a3 + v[3];
        const float mx = fmaxf(fmaxf(f0, f1), fmaxf(f2, f3));
        const float logZ = mx + __logf(__expf(f0 - mx) + __expf(f1 - mx) +
                                       __expf(f2 - mx) + __expf(f3 - mx));
        const float r = logZ - v[4];
        // Deterministic fixed-point accumulation (integer adds associative).
        long long q = llrint((double)r * FIXED_SCALE);
        atomicAdd(&g_buckets[b & (NBUCKETS - 1)], (unsigned long long)q);
    }

    // ---- ticket: last block folds the buckets ----
    __syncthreads();          // all warps' bucket atomics issued
    __threadfence();
    if (threadIdx.x == 0) {
        unsigned int old = atomicAdd(&g_ticket, 1u);
        // 2^32 % gridDim.x == 0 (grid = 2048): replay-safe without a reset.
        s_last = ((old % gridDim.x) == gridDim.x - 1u);
    }
    __syncthreads();

    if (s_last && threadIdx.x == 0) {
        long long total = 0;
        #pragma unroll
        for (int i = 0; i < NBUCKETS; ++i) total += (long long)g_buckets[i];
        out[0] = (float)(((double)total / FIXED_SCALE) / (double)B);
        #pragma unroll
        for (int i = 0; i < NBUCKETS; ++i) g_buckets[i] = 0ULL;  // next replay
    }
}

extern "C" void kernel_launch(void* const* d_in, const int* in_sizes, int n_in,
                              void* d_out, int out_size)
{
    const float* emissions   = (const float*)d_in[0];
    const void*  tags        = (const void*)d_in[1];
    const void*  mask        = (const void*)d_in[2];
    const float* transitions = (const float*)d_in[3];

    const int B = in_sizes[0] / (T_LEN * 4);   // emissions: B*T*4 floats

    crf_warp_kernel<<<B / WARPS_PER_BLOCK, NTHREADS>>>(
        emissions, tags, mask, transitions, (float*)d_out, B);
}

// round 10
// speedup vs baseline: 1.6364x; 1.2379x over previous
#include <cuda_runtime.h>

// LinearChainCRF: mean(logZ - gold) over B=16384 sequences of T=512, N_TAGS=4.
//
// Algebra: the reference's logsumexp is over the LAST axis (j); alpha[i] is
// constant in j, so the "scan" is purely additive:
//   alpha_T[i] = em[0,i] + sum_{t>=1} mask_t * log(s_i(t)),
//   s_i(t)     = sum_j exp(trans[i,j]) * exp(em[t,j])   (|e| <~ 6 -> no norm)
//   logZ       = logsumexp_i(alpha_T[i]);  result = mean(logZ - gold).
//
// R10: hot loop template-specialized on (tags int32/int64 x mask 1/4/8B) --
// branch-free unrolled bodies, dispatched once per warp after the probes.
// Cuts per-iteration branch scaffolding and dead-path register liveness
// (R9: regs=40 -> 6 blocks/SM). Warp-per-sequence, 16 t/thread stride-32.
// Fused deterministic reduction: Q32.32 integer bucket atomics + ticket.

#define T_LEN 512
#define WARPS_PER_BLOCK 8
#define NTHREADS (32 * WARPS_PER_BLOCK)
#define NBUCKETS 64
#define FIXED_SCALE 4294967296.0   // 2^32

__device__ unsigned long long g_buckets[NBUCKETS];  // zero at load; self-reset
__device__ unsigned int g_ticket;                   // used modulo grid size

// Branch-free specialized warp worker. Returns logZ-gold (valid on lane 0).
// No block-level synchronization inside (safe under divergent dispatch).
template <bool IS64, int MW>
__device__ __forceinline__ float warp_crf(int base, int lane,
                                          const float4* __restrict__ em4,
                                          const void* __restrict__ tags_raw,
                                          const void* __restrict__ mask_raw,
                                          const float* trans_s,
                                          const float eT[16])
{
    const long long* tg64 = (const long long*)tags_raw;
    const int* tg32 = (const int*)tags_raw;
    const unsigned full = 0xffffffffu;

    float c0 = 0.f, c1 = 0.f, c2 = 0.f, c3 = 0.f, gold = 0.f;
    float a0 = 0.f, a1 = 0.f, a2 = 0.f, a3 = 0.f;   // alpha0 (lane 0 only)

    #pragma unroll
    for (int chunk = 0; chunk < 4; ++chunk) {
        float pr0 = 1.f, pr1 = 1.f, pr2 = 1.f, pr3 = 1.f;
        #pragma unroll
        for (int u = 0; u < 4; ++u) {
            const int t = (chunk * 4 + u) * 32 + lane;
            const int idx = base + t;

            const float4 e = em4[idx];

            int tag, ptag = 0;
            if (IS64) {
                tag = (int)tg64[idx];
                if (t > 0) ptag = (int)tg64[idx - 1];
            } else {
                tag = tg32[idx];
                if (t > 0) ptag = tg32[idx - 1];
            }
            float m;
            if (MW == 1)      m = ((const unsigned char*)mask_raw)[idx] ? 1.0f : 0.0f;
            else if (MW == 4) m = ((const int*)mask_raw)[idx] ? 1.0f : 0.0f;
            else              m = ((const long long*)mask_raw)[idx] ? 1.0f : 0.0f;

            const float etag = (tag == 0) ? e.x : (tag == 1) ? e.y
                             : (tag == 2) ? e.z : e.w;

            if (t == 0) {
                gold += m * etag;
                a0 = e.x; a1 = e.y; a2 = e.z; a3 = e.w;
            } else {
                gold += m * (etag + trans_s[ptag * 4 + tag]);
                const float q0 = __expf(e.x);
                const float q1 = __expf(e.y);
                const float q2 = __expf(e.z);
                const float q3 = __expf(e.w);
                float s0 = eT[0]  * q0 + eT[1]  * q1 + eT[2]  * q2 + eT[3]  * q3;
                float s1 = eT[4]  * q0 + eT[5]  * q1 + eT[6]  * q2 + eT[7]  * q3;
                float s2 = eT[8]  * q0 + eT[9]  * q1 + eT[10] * q2 + eT[11] * q3;
                float s3 = eT[12] * q0 + eT[13] * q1 + eT[14] * q2 + eT[15] * q3;
                pr0 *= (m != 0.f) ? s0 : 1.0f;
                pr1 *= (m != 0.f) ? s1 : 1.0f;
                pr2 *= (m != 0.f) ? s2 : 1.0f;
                pr3 *= (m != 0.f) ? s3 : 1.0f;
            }
        }
        c0 += __logf(pr0);
        c1 += __logf(pr1);
        c2 += __logf(pr2);
        c3 += __logf(pr3);
    }

    // warp-wide sums of {c0,c1,c2,c3,gold}
    float v[5] = {c0, c1, c2, c3, gold};
    #pragma unroll
    for (int k = 0; k < 5; ++k) {
        float x = v[k];
        x += __shfl_xor_sync(full, x, 16);
        x += __shfl_xor_sync(full, x, 8);
        x += __shfl_xor_sync(full, x, 4);
        x += __shfl_xor_sync(full, x, 2);
        x += __shfl_xor_sync(full, x, 1);
        v[k] = x;
    }

    const float f0 = a0 + v[0];
    const float f1 = a1 + v[1];
    const float f2 = a2 + v[2];
    const float f3 = a3 + v[3];
    const float mx = fmaxf(fmaxf(f0, f1), fmaxf(f2, f3));
    const float logZ = mx + __logf(__expf(f0 - mx) + __expf(f1 - mx) +
                                   __expf(f2 - mx) + __expf(f3 - mx));
    return logZ - v[4];
}

__global__ __launch_bounds__(NTHREADS)
void crf_warp_kernel(const float* __restrict__ emissions,
                     const void* __restrict__ tags_raw,
                     const void* __restrict__ mask_raw,
                     const float* __restrict__ transitions,
                     float* __restrict__ out, int B)
{
    __shared__ float trans_s[16];
    __shared__ float expT_s[16];
    __shared__ int s_last;

    const int lane = threadIdx.x & 31;
    const int warp = threadIdx.x >> 5;
    const int b = blockIdx.x * WARPS_PER_BLOCK + warp;
    const unsigned full = 0xffffffffu;

    if (threadIdx.x < 16) {
        float tv = transitions[threadIdx.x];
        trans_s[threadIdx.x] = tv;
        expT_s[threadIdx.x] = __expf(tv);
    }
    __syncthreads();

    // ---- warp-parallel dtype probes (first words; L2-resident after block 0) --
    const int* tags32p = (const int*)tags_raw;
    const unsigned int* mask32p = (const unsigned int*)mask_raw;
    // tags int64 <=> odd int32 words all zero (tags in [0,4); P(miss)~(1/4)^32)
    const int tag_is64 = (__ballot_sync(full, tags32p[2 * lane + 1] != 0) == 0u);
    // mask: u8 -> hi bytes of words set; i32 -> odd words nonzero; i64 -> neither
    const unsigned int hi = __ballot_sync(full, (mask32p[lane] & 0xFFFFFF00u) != 0u);
    const unsigned int od = __ballot_sync(full, mask32p[2 * lane + 1] != 0u);
    const int mask_w = hi ? 1 : (od ? 4 : 8);

    float eT[16];
    #pragma unroll
    for (int i = 0; i < 16; ++i) eT[i] = expT_s[i];

    const int base = b * T_LEN;                      // <= 8.4M: 32-bit safe
    const float4* em4 = (const float4*)emissions;

    // One-time uniform dispatch to the branch-free specialized loop.
    float r;
    if (tag_is64) {
        if (mask_w == 1)
            r = warp_crf<true, 1>(base, lane, em4, tags_raw, mask_raw, trans_s, eT);
        else if (mask_w == 4)
            r = warp_crf<true, 4>(base, lane, em4, tags_raw, mask_raw, trans_s, eT);
        else
            r = warp_crf<true, 8>(base, lane, em4, tags_raw, mask_raw, trans_s, eT);
    } else {
        if (mask_w == 1)
            r = warp_crf<false, 1>(base, lane, em4, tags_raw, mask_raw, trans_s, eT);
        else if (mask_w == 4)
            r = warp_crf<false, 4>(base, lane, em4, tags_raw, mask_raw, trans_s, eT);
        else
            r = warp_crf<false, 8>(base, lane, em4, tags_raw, mask_raw, trans_s, eT);
    }

    if (lane == 0) {
        // Deterministic fixed-point accumulation (integer adds associative).
        long long q = llrint((double)r * FIXED_SCALE);
        atomicAdd(&g_buckets[b & (NBUCKETS - 1)], (unsigned long long)q);
    }

    // ---- ticket: last block folds the buckets ----
    __syncthreads();          // all warps' bucket atomics issued
    __threadfence();
    if (threadIdx.x == 0) {
        unsigned int old = atomicAdd(&g_ticket, 1u);
        // 2^32 % gridDim.x == 0 (grid = 2048): replay-safe without a reset.
        s_last = ((old % gridDim.x) == gridDim.x - 1u);
    }
    __syncthreads();

    if (s_last && threadIdx.x == 0) {
        long long total = 0;
        #pragma unroll
        for (int i = 0; i < NBUCKETS; ++i) total += (long long)g_buckets[i];
        out[0] = (float)(((double)total / FIXED_SCALE) / (double)B);
        #pragma unroll
        for (int i = 0; i < NBUCKETS; ++i) g_buckets[i] = 0ULL;  // next replay
    }
}

extern "C" void kernel_launch(void* const* d_in, const int* in_sizes, int n_in,
                              void* d_out, int out_size)
{
    const float* emissions   = (const float*)d_in[0];
    const void*  tags        = (const void*)d_in[1];
    const void*  mask        = (const void*)d_in[2];
    const float* transitions = (const float*)d_in[3];

    const int B = in_sizes[0] / (T_LEN * 4);   // emissions: B*T*4 floats

    crf_warp_kernel<<<B / WARPS_PER_BLOCK, NTHREADS>>>(
        emissions, tags, mask, transitions, (float*)d_out, B);
}

// round 12
// speedup vs baseline: 1.8665x; 1.1406x over previous
#include <cuda_runtime.h>

// LinearChainCRF: mean(logZ - gold) over B=16384 sequences of T=512, N_TAGS=4.
//
// Algebra: the reference's logsumexp is over the LAST axis (j); alpha[i] is
// constant in j, so the "scan" is purely additive:
//   alpha_T[i] = em[0,i] + sum_{t>=1} mask_t * log(s_i(t)),
//   s_i(t)     = sum_j exp(trans[i,j]) * exp(em[t,j])   (|e| <~ 6 -> no norm)
//   logZ       = logsumexp_i(alpha_T[i]);  result = mean(logZ - gold).
//
// R12 = R11 resubmitted (container infra failure, kernel never ran):
// R10's template-specialized branch-free hot loop (warp-per-sequence,
// 16 t/thread stride-32; fused deterministic Q32.32 reduction) + ONE change:
// __launch_bounds__(256, 8) forces 32 regs -> 8 blocks/SM -> 64 warps/SM.
// R10 profile was latency-bound (DRAM 44%, issue 42%, occ 64%, nothing
// saturated); +33% resident warps is the direct lever.

#define T_LEN 512
#define WARPS_PER_BLOCK 8
#define NTHREADS (32 * WARPS_PER_BLOCK)
#define NBUCKETS 64
#define FIXED_SCALE 4294967296.0   // 2^32

__device__ unsigned long long g_buckets[NBUCKETS];  // zero at load; self-reset
__device__ unsigned int g_ticket;                   // used modulo grid size

// Branch-free specialized warp worker. Returns logZ-gold (valid on lane 0).
// No block-level synchronization inside (safe under divergent dispatch).
template <bool IS64, int MW>
__device__ __forceinline__ float warp_crf(int base, int lane,
                                          const float4* __restrict__ em4,
                                          const void* __restrict__ tags_raw,
                                          const void* __restrict__ mask_raw,
                                          const float* trans_s,
                                          const float eT[16])
{
    const long long* tg64 = (const long long*)tags_raw;
    const int* tg32 = (const int*)tags_raw;
    const unsigned full = 0xffffffffu;

    float c0 = 0.f, c1 = 0.f, c2 = 0.f, c3 = 0.f, gold = 0.f;
    float a0 = 0.f, a1 = 0.f, a2 = 0.f, a3 = 0.f;   // alpha0 (lane 0 only)

    #pragma unroll
    for (int chunk = 0; chunk < 4; ++chunk) {
        float pr0 = 1.f, pr1 = 1.f, pr2 = 1.f, pr3 = 1.f;
        #pragma unroll
        for (int u = 0; u < 4; ++u) {
            const int t = (chunk * 4 + u) * 32 + lane;
            const int idx = base + t;

            const float4 e = em4[idx];

            int tag, ptag = 0;
            if (IS64) {
                tag = (int)tg64[idx];
                if (t > 0) ptag = (int)tg64[idx - 1];
            } else {
                tag = tg32[idx];
                if (t > 0) ptag = tg32[idx - 1];
            }
            float m;
            if (MW == 1)      m = ((const unsigned char*)mask_raw)[idx] ? 1.0f : 0.0f;
            else if (MW == 4) m = ((const int*)mask_raw)[idx] ? 1.0f : 0.0f;
            else              m = ((const long long*)mask_raw)[idx] ? 1.0f : 0.0f;

            const float etag = (tag == 0) ? e.x : (tag == 1) ? e.y
                             : (tag == 2) ? e.z : e.w;

            if (t == 0) {
                gold += m * etag;
                a0 = e.x; a1 = e.y; a2 = e.z; a3 = e.w;
            } else {
                gold += m * (etag + trans_s[ptag * 4 + tag]);
                const float q0 = __expf(e.x);
                const float q1 = __expf(e.y);
                const float q2 = __expf(e.z);
                const float q3 = __expf(e.w);
                float s0 = eT[0]  * q0 + eT[1]  * q1 + eT[2]  * q2 + eT[3]  * q3;
                float s1 = eT[4]  * q0 + eT[5]  * q1 + eT[6]  * q2 + eT[7]  * q3;
                float s2 = eT[8]  * q0 + eT[9]  * q1 + eT[10] * q2 + eT[11] * q3;
                float s3 = eT[12] * q0 + eT[13] * q1 + eT[14] * q2 + eT[15] * q3;
                pr0 *= (m != 0.f) ? s0 : 1.0f;
                pr1 *= (m != 0.f) ? s1 : 1.0f;
                pr2 *= (m != 0.f) ? s2 : 1.0f;
                pr3 *= (m != 0.f) ? s3 : 1.0f;
            }
        }
        c0 += __logf(pr0);
        c1 += __logf(pr1);
        c2 += __logf(pr2);
        c3 += __logf(pr3);
    }

    // warp-wide sums of {c0,c1,c2,c3,gold}
    float v[5] = {c0, c1, c2, c3, gold};
    #pragma unroll
    for (int k = 0; k < 5; ++k) {
        float x = v[k];
        x += __shfl_xor_sync(full, x, 16);
        x += __shfl_xor_sync(full, x, 8);
        x += __shfl_xor_sync(full, x, 4);
        x += __shfl_xor_sync(full, x, 2);
        x += __shfl_xor_sync(full, x, 1);
        v[k] = x;
    }

    const float f0 = a0 + v[0];
    const float f1 = a1 + v[1];
    const float f2 = a2 + v[2];
    const float f3 = a3 + v[3];
    const float mx = fmaxf(fmaxf(f0, f1), fmaxf(f2, f3));
    const float logZ = mx + __logf(__expf(f0 - mx) + __expf(f1 - mx) +
                                   __expf(f2 - mx) + __expf(f3 - mx));
    return logZ - v[4];
}

__global__ __launch_bounds__(NTHREADS, 8)
void crf_warp_kernel(const float* __restrict__ emissions,
                     const void* __restrict__ tags_raw,
                     const void* __restrict__ mask_raw,
                     const float* __restrict__ transitions,
                     float* __restrict__ out, int B)
{
    __shared__ float trans_s[16];
    __shared__ float expT_s[16];
    __shared__ int s_last;

    const int lane = threadIdx.x & 31;
    const int warp = threadIdx.x >> 5;
    const int b = blockIdx.x * WARPS_PER_BLOCK + warp;
    const unsigned full = 0xffffffffu;

    if (threadIdx.x < 16) {
        float tv = transitions[threadIdx.x];
        trans_s[threadIdx.x] = tv;
        expT_s[threadIdx.x] = __expf(tv);
    }
    __syncthreads();

    // ---- warp-parallel dtype probes (first words; L2-resident after block 0) --
    const int* tags32p = (const int*)tags_raw;
    const unsigned int* mask32p = (const unsigned int*)mask_raw;
    // tags int64 <=> odd int32 words all zero (tags in [0,4); P(miss)~(1/4)^32)
    const int tag_is64 = (__ballot_sync(full, tags32p[2 * lane + 1] != 0) == 0u);
    // mask: u8 -> hi bytes of words set; i32 -> odd words nonzero; i64 -> neither
    const unsigned int hi = __ballot_sync(full, (mask32p[lane] & 0xFFFFFF00u) != 0u);
    const unsigned int od = __ballot_sync(full, mask32p[2 * lane + 1] != 0u);
    const int mask_w = hi ? 1 : (od ? 4 : 8);

    float eT[16];
    #pragma unroll
    for (int i = 0; i < 16; ++i) eT[i] = expT_s[i];

    const int base = b * T_LEN;                      // <= 8.4M: 32-bit safe
    const float4* em4 = (const float4*)emissions;

    // One-time uniform dispatch to the branch-free specialized loop.
    float r;
    if (tag_is64) {
        if (mask_w == 1)
            r = warp_crf<true, 1>(base, lane, em4, tags_raw, mask_raw, trans_s, eT);
        else if (mask_w == 4)
            r = warp_crf<true, 4>(base, lane, em4, tags_raw, mask_raw, trans_s, eT);
        else
            r = warp_crf<true, 8>(base, lane, em4, tags_raw, mask_raw, trans_s, eT);
    } else {
        if (mask_w == 1)
            r = warp_crf<false, 1>(base, lane, em4, tags_raw, mask_raw, trans_s, eT);
        else if (mask_w == 4)
            r = warp_crf<false, 4>(base, lane, em4, tags_raw, mask_raw, trans_s, eT);
        else
            r = warp_crf<false, 8>(base, lane, em4, tags_raw, mask_raw, trans_s, eT);
    }

    if (lane == 0) {
        // Deterministic fixed-point accumulation (integer adds associative).
        long long q = llrint((double)r * FIXED_SCALE);
        atomicAdd(&g_buckets[b & (NBUCKETS - 1)], (unsigned long long)q);
    }

    // ---- ticket: last block folds the buckets ----
    __syncthreads();          // all warps' bucket atomics issued
    __threadfence();
    if (threadIdx.x == 0) {
        unsigned int old = atomicAdd(&g_ticket, 1u);
        // 2^32 % gridDim.x == 0 (grid = 2048): replay-safe without a reset.
        s_last = ((old % gridDim.x) == gridDim.x - 1u);
    }
    __syncthreads();

    if (s_last && threadIdx.x == 0) {
        long long total = 0;
        #pragma unroll
        for (int i = 0; i < NBUCKETS; ++i) total += (long long)g_buckets[i];
        out[0] = (float)(((double)total / FIXED_SCALE) / (double)B);
        #pragma unroll
        for (int i = 0; i < NBUCKETS; ++i) g_buckets[i] = 0ULL;  // next replay
    }
}

extern "C" void kernel_launch(void* const* d_in, const int* in_sizes, int n_in,
                              void* d_out, int out_size)
{
    const float* emissions   = (const float*)d_in[0];
    const void*  tags        = (const void*)d_in[1];
    const void*  mask        = (const void*)d_in[2];
    const float* transitions = (const float*)d_in[3];

    const int B = in_sizes[0] / (T_LEN * 4);   // emissions: B*T*4 floats

    crf_warp_kernel<<<B / WARPS_PER_BLOCK, NTHREADS>>>(
        emissions, tags, mask, transitions, (float*)d_out, B);
}